// round 12
// baseline (speedup 1.0000x reference)
#include <cuda_runtime.h>
#include <math.h>

// EGNN layer collapsed to the diagonal. Per row r:
//   t1 = silu(h@(We1a+We1b) + sqrt(EPS)*We1[2F] + be1)
//   t2 = silu(t1@We2 + be2)
//   att = sigmoid(t2.Wa + ba)                 [warp-uniform scalar]
//   t3 = silu(bn1 + h@Wn1a + att*(t2@Wn1b))   [att factored out]
//   out = t3@Wn2 + bn2
// R12 = R10 + per-layer weight PRE-HOIST: each layer first loads its 8
// weight float4s from smem into a register array (8 independent LDS.128,
// latency overlapped), then runs a pure shfl+FFMA stream. Breaks the
// per-q LDS->shfl->FFMA serial chain that pinned issue at ~20%.
// Uniform 147 blocks x 7 warps, 2 rows/warp, transposed smem weights.

#define SQRT_EPS 0.0031622776601683794f  // sqrt(1e-5)
#define FULL 0xffffffffu
#define PAD 36
#define WARPS_PER_BLOCK 7
#define ROWS_PER_BLOCK (WARPS_PER_BLOCK * 2)

__device__ __forceinline__ float silu_f(float v) {
    return __fdividef(v, 1.0f + __expf(-v));
}
__device__ __forceinline__ float sigmoid_f(float v) {
    return __fdividef(1.0f, 1.0f + __expf(-v));
}

__global__ void __launch_bounds__(32 * WARPS_PER_BLOCK, 1)
egnn_diag_kernel(const float* __restrict__ h,
                 const float* __restrict__ x,
                 const float* __restrict__ We1, const float* __restrict__ be1,
                 const float* __restrict__ We2, const float* __restrict__ be2,
                 const float* __restrict__ Wa,  const float* __restrict__ ba,
                 const float* __restrict__ Wn1, const float* __restrict__ bn1,
                 const float* __restrict__ Wn2, const float* __restrict__ bn2,
                 float* __restrict__ out, float* __restrict__ xout, int R)
{
    // transposed: s[j*PAD + f] = W[f][j]; lane j reads its column via LDS.128
    __shared__ __align__(16) float s_w1 [32 * PAD];  // We1a+We1b folded
    __shared__ __align__(16) float s_wna[32 * PAD];  // Wn1[0:F]
    __shared__ __align__(16) float s_wnb[32 * PAD];  // Wn1[F:2F]
    __shared__ __align__(16) float s_we2[32 * PAD];
    __shared__ __align__(16) float s_wn2[32 * PAD];

    const int tid  = threadIdx.x;
    const int lane = tid & 31;
    const int r0   = blockIdx.x * ROWS_PER_BLOCK + (tid >> 5) * 2;
    const int r1   = r0 + 1;

    // ---- cooperative transposing fill: 256 float4 slots, 224 threads ----
    for (int i = tid; i < 256; i += 32 * WARPS_PER_BLOCK) {
        const int f  = i >> 3;            // 0..31 (row of W)
        const int j0 = (i & 7) * 4;       // col group
        const float4 a  = ((const float4*)We1)[i];
        const float4 b  = ((const float4*)We1)[256 + i];
        s_w1[(j0 + 0) * PAD + f] = a.x + b.x;
        s_w1[(j0 + 1) * PAD + f] = a.y + b.y;
        s_w1[(j0 + 2) * PAD + f] = a.z + b.z;
        s_w1[(j0 + 3) * PAD + f] = a.w + b.w;
        const float4 na = ((const float4*)Wn1)[i];
        s_wna[(j0 + 0) * PAD + f] = na.x;
        s_wna[(j0 + 1) * PAD + f] = na.y;
        s_wna[(j0 + 2) * PAD + f] = na.z;
        s_wna[(j0 + 3) * PAD + f] = na.w;
        const float4 nb = ((const float4*)Wn1)[256 + i];
        s_wnb[(j0 + 0) * PAD + f] = nb.x;
        s_wnb[(j0 + 1) * PAD + f] = nb.y;
        s_wnb[(j0 + 2) * PAD + f] = nb.z;
        s_wnb[(j0 + 3) * PAD + f] = nb.w;
        const float4 e2 = ((const float4*)We2)[i];
        s_we2[(j0 + 0) * PAD + f] = e2.x;
        s_we2[(j0 + 1) * PAD + f] = e2.y;
        s_we2[(j0 + 2) * PAD + f] = e2.z;
        s_we2[(j0 + 3) * PAD + f] = e2.w;
        const float4 n2 = ((const float4*)Wn2)[i];
        s_wn2[(j0 + 0) * PAD + f] = n2.x;
        s_wn2[(j0 + 1) * PAD + f] = n2.y;
        s_wn2[(j0 + 2) * PAD + f] = n2.z;
        s_wn2[(j0 + 3) * PAD + f] = n2.w;
    }

    // ---- independent per-warp front work (overlaps fill latency) ----
    const bool has0 = (r0 < R);
    const bool has1 = (r1 < R);
    const float hv0 = has0 ? h[r0 * 32 + lane] : 0.f;
    const float hv1 = has1 ? h[r1 * 32 + lane] : 0.f;

    if (lane < 6 && r0 * 3 + lane < R * 3)       // x rows r0,r1 (6 floats)
        xout[r0 * 3 + lane] = x[r0 * 3 + lane];

    const float b1  = be1[lane] + SQRT_EPS * We1[64 * 32 + lane];
    const float b2  = be2[lane];
    const float wa  = Wa[lane];
    const float ba0 = ba[0];
    const float b3  = bn1[lane];
    const float b4  = bn2[lane];

    __syncthreads();
    if (!has0) return;

    const int col = lane * PAD;
    float t1_0, t1_1, sh0, sh1;

    // ================= layer 1 + S_h fused (weights pre-hoisted) =========
    {
        float4 w1[8], wn[8];
        #pragma unroll
        for (int q = 0; q < 8; ++q) w1[q] = *(const float4*)&s_w1 [col + 4 * q];
        #pragma unroll
        for (int q = 0; q < 8; ++q) wn[q] = *(const float4*)&s_wna[col + 4 * q];

        float a00 = b1, a10 = 0.f, a01 = b1, a11 = 0.f;
        float p00 = 0.f, p10 = 0.f, p01 = 0.f, p11 = 0.f;
        #pragma unroll
        for (int q = 0; q < 8; ++q) {
            const float h00 = __shfl_sync(FULL, hv0, 4 * q + 0);
            const float h01 = __shfl_sync(FULL, hv0, 4 * q + 1);
            const float h02 = __shfl_sync(FULL, hv0, 4 * q + 2);
            const float h03 = __shfl_sync(FULL, hv0, 4 * q + 3);
            const float h10 = __shfl_sync(FULL, hv1, 4 * q + 0);
            const float h11 = __shfl_sync(FULL, hv1, 4 * q + 1);
            const float h12 = __shfl_sync(FULL, hv1, 4 * q + 2);
            const float h13 = __shfl_sync(FULL, hv1, 4 * q + 3);
            a00 += h00 * w1[q].x;  a10 += h01 * w1[q].y;
            a00 += h02 * w1[q].z;  a10 += h03 * w1[q].w;
            a01 += h10 * w1[q].x;  a11 += h11 * w1[q].y;
            a01 += h12 * w1[q].z;  a11 += h13 * w1[q].w;
            p00 += h00 * wn[q].x;  p10 += h01 * wn[q].y;
            p00 += h02 * wn[q].z;  p10 += h03 * wn[q].w;
            p01 += h10 * wn[q].x;  p11 += h11 * wn[q].y;
            p01 += h12 * wn[q].z;  p11 += h13 * wn[q].w;
        }
        t1_0 = silu_f(a00 + a10);
        t1_1 = silu_f(a01 + a11);
        sh0 = p00 + p10;
        sh1 = p01 + p11;
    }

    // ================= layer 2 (weights pre-hoisted) =================
    float t2_0, t2_1;
    {
        float4 w2[8];
        #pragma unroll
        for (int q = 0; q < 8; ++q) w2[q] = *(const float4*)&s_we2[col + 4 * q];

        float a00 = b2, a10 = 0.f, a01 = b2, a11 = 0.f;
        #pragma unroll
        for (int q = 0; q < 8; ++q) {
            a00 += __shfl_sync(FULL, t1_0, 4 * q + 0) * w2[q].x;
            a10 += __shfl_sync(FULL, t1_0, 4 * q + 1) * w2[q].y;
            a00 += __shfl_sync(FULL, t1_0, 4 * q + 2) * w2[q].z;
            a10 += __shfl_sync(FULL, t1_0, 4 * q + 3) * w2[q].w;
            a01 += __shfl_sync(FULL, t1_1, 4 * q + 0) * w2[q].x;
            a11 += __shfl_sync(FULL, t1_1, 4 * q + 1) * w2[q].y;
            a01 += __shfl_sync(FULL, t1_1, 4 * q + 2) * w2[q].z;
            a11 += __shfl_sync(FULL, t1_1, 4 * q + 3) * w2[q].w;
        }
        t2_0 = silu_f(a00 + a10);
        t2_1 = silu_f(a01 + a11);
    }

    // ===== att butterfly overlapped with S_t2 = t2 @ Wn1b (pre-hoisted) ===
    float att0, att1, st0, st1;
    {
        float4 wb[8];
        #pragma unroll
        for (int q = 0; q < 8; ++q) wb[q] = *(const float4*)&s_wnb[col + 4 * q];

        float s0 = t2_0 * wa;
        float s1 = t2_1 * wa;
        float p00 = 0.f, p10 = 0.f, p01 = 0.f, p11 = 0.f;
        #pragma unroll
        for (int q = 0; q < 8; ++q) {
            p00 += __shfl_sync(FULL, t2_0, 4 * q + 0) * wb[q].x;
            p10 += __shfl_sync(FULL, t2_0, 4 * q + 1) * wb[q].y;
            p00 += __shfl_sync(FULL, t2_0, 4 * q + 2) * wb[q].z;
            p10 += __shfl_sync(FULL, t2_0, 4 * q + 3) * wb[q].w;
            p01 += __shfl_sync(FULL, t2_1, 4 * q + 0) * wb[q].x;
            p11 += __shfl_sync(FULL, t2_1, 4 * q + 1) * wb[q].y;
            p01 += __shfl_sync(FULL, t2_1, 4 * q + 2) * wb[q].z;
            p11 += __shfl_sync(FULL, t2_1, 4 * q + 3) * wb[q].w;
        }
        #pragma unroll
        for (int off = 16; off > 0; off >>= 1) {
            s0 += __shfl_xor_sync(FULL, s0, off);
            s1 += __shfl_xor_sync(FULL, s1, off);
        }
        att0 = sigmoid_f(s0 + ba0);
        att1 = sigmoid_f(s1 + ba0);
        st0 = p00 + p10;
        st1 = p01 + p11;
    }

    // ---- layer 3 epilogue ----
    const float t3_0 = silu_f(b3 + sh0 + att0 * st0);
    const float t3_1 = silu_f(b3 + sh1 + att1 * st1);

    // ================= layer 4 (weights pre-hoisted) =================
    {
        float4 w4[8];
        #pragma unroll
        for (int q = 0; q < 8; ++q) w4[q] = *(const float4*)&s_wn2[col + 4 * q];

        float a00 = b4, a10 = 0.f, a01 = b4, a11 = 0.f;
        #pragma unroll
        for (int q = 0; q < 8; ++q) {
            a00 += __shfl_sync(FULL, t3_0, 4 * q + 0) * w4[q].x;
            a10 += __shfl_sync(FULL, t3_0, 4 * q + 1) * w4[q].y;
            a00 += __shfl_sync(FULL, t3_0, 4 * q + 2) * w4[q].z;
            a10 += __shfl_sync(FULL, t3_0, 4 * q + 3) * w4[q].w;
            a01 += __shfl_sync(FULL, t3_1, 4 * q + 0) * w4[q].x;
            a11 += __shfl_sync(FULL, t3_1, 4 * q + 1) * w4[q].y;
            a01 += __shfl_sync(FULL, t3_1, 4 * q + 2) * w4[q].z;
            a11 += __shfl_sync(FULL, t3_1, 4 * q + 3) * w4[q].w;
        }
        out[r0 * 32 + lane] = a00 + a10;
        if (has1) out[r1 * 32 + lane] = a01 + a11;
    }
}

extern "C" void kernel_launch(void* const* d_in, const int* in_sizes, int n_in,
                              void* d_out, int out_size)
{
    const float* h   = (const float*)d_in[0];
    const float* x   = (const float*)d_in[1];
    const float* We1 = (const float*)d_in[2];
    const float* be1 = (const float*)d_in[3];
    const float* We2 = (const float*)d_in[4];
    const float* be2 = (const float*)d_in[5];
    const float* Wa  = (const float*)d_in[6];
    const float* ba  = (const float*)d_in[7];
    const float* Wn1 = (const float*)d_in[8];
    const float* bn1 = (const float*)d_in[9];
    const float* Wn2 = (const float*)d_in[10];
    const float* bn2 = (const float*)d_in[11];

    const int R = in_sizes[0] / 32;          // B*N rows
    float* out  = (float*)d_out;             // [R, 32]
    float* xout = out + (size_t)R * 32;      // [R, 3] passthrough

    const int threads = 32 * WARPS_PER_BLOCK;                       // 224
    const int blocks  = (R + ROWS_PER_BLOCK - 1) / ROWS_PER_BLOCK;  // 147
    egnn_diag_kernel<<<blocks, threads>>>(h, x, We1, be1, We2, be2, Wa, ba,
                                          Wn1, bn1, Wn2, bn2, out, xout, R);
}

// round 13
// speedup vs baseline: 1.0332x; 1.0332x over previous
#include <cuda_runtime.h>
#include <math.h>

// EGNN layer collapsed to the diagonal. Per row r:
//   t1 = silu(h@(We1a+We1b) + sqrt(EPS)*We1[2F] + be1)
//   t2 = silu(t1@We2 + be2)
//   att = sigmoid(t2.Wa + ba)                 [warp-uniform scalar]
//   t3 = silu(bn1 + h@Wn1a + att*(t2@Wn1b))   [att factored out]
//   out = t3@Wn2 + bn2
// R13 = R10 + critical-path cuts:
//  (a) no shfl_xor butterfly: att dot computed redundantly per lane by
//      reusing the S_t2 loop's t2 broadcasts against Wa[f] (pre-hoisted
//      from smem) -> identical value on all lanes, ~150 serial cyc saved.
//  (b) h/x/bias LDGs front-loaded before the smem fill.
// Uniform 147 blocks x 7 warps, 2 rows/warp, transposed smem weights
// read as lane-column LDS.128 (PAD 36, conflict-free).

#define SQRT_EPS 0.0031622776601683794f  // sqrt(1e-5)
#define FULL 0xffffffffu
#define PAD 36
#define WARPS_PER_BLOCK 7
#define ROWS_PER_BLOCK (WARPS_PER_BLOCK * 2)

__device__ __forceinline__ float silu_f(float v) {
    return __fdividef(v, 1.0f + __expf(-v));
}
__device__ __forceinline__ float sigmoid_f(float v) {
    return __fdividef(1.0f, 1.0f + __expf(-v));
}

__global__ void __launch_bounds__(32 * WARPS_PER_BLOCK, 1)
egnn_diag_kernel(const float* __restrict__ h,
                 const float* __restrict__ x,
                 const float* __restrict__ We1, const float* __restrict__ be1,
                 const float* __restrict__ We2, const float* __restrict__ be2,
                 const float* __restrict__ Wa,  const float* __restrict__ ba,
                 const float* __restrict__ Wn1, const float* __restrict__ bn1,
                 const float* __restrict__ Wn2, const float* __restrict__ bn2,
                 float* __restrict__ out, float* __restrict__ xout, int R)
{
    // transposed: s[j*PAD + f] = W[f][j]; lane j reads its column via LDS.128
    __shared__ __align__(16) float s_w1 [32 * PAD];  // We1a+We1b folded
    __shared__ __align__(16) float s_wna[32 * PAD];  // Wn1[0:F]
    __shared__ __align__(16) float s_wnb[32 * PAD];  // Wn1[F:2F]
    __shared__ __align__(16) float s_we2[32 * PAD];
    __shared__ __align__(16) float s_wn2[32 * PAD];
    __shared__ __align__(16) float s_wav[32];        // Wa, broadcast by f

    const int tid  = threadIdx.x;
    const int lane = tid & 31;
    const int r0   = blockIdx.x * ROWS_PER_BLOCK + (tid >> 5) * 2;
    const int r1   = r0 + 1;

    // ---- front-load all independent per-warp LDGs (layer-1 roots) ----
    const bool has0 = (r0 < R);
    const bool has1 = (r1 < R);
    const float hv0 = has0 ? h[r0 * 32 + lane] : 0.f;
    const float hv1 = has1 ? h[r1 * 32 + lane] : 0.f;

    if (lane < 6 && r0 * 3 + lane < R * 3)       // x rows r0,r1 (6 floats)
        xout[r0 * 3 + lane] = x[r0 * 3 + lane];

    const float b1  = be1[lane] + SQRT_EPS * We1[64 * 32 + lane];
    const float b2  = be2[lane];
    const float ba0 = ba[0];
    const float b3  = bn1[lane];
    const float b4  = bn2[lane];

    // ---- cooperative transposing fill: 256 float4 slots, 224 threads ----
    for (int i = tid; i < 256; i += 32 * WARPS_PER_BLOCK) {
        const int f  = i >> 3;            // 0..31 (row of W)
        const int j0 = (i & 7) * 4;       // col group
        const float4 a  = ((const float4*)We1)[i];
        const float4 b  = ((const float4*)We1)[256 + i];
        s_w1[(j0 + 0) * PAD + f] = a.x + b.x;
        s_w1[(j0 + 1) * PAD + f] = a.y + b.y;
        s_w1[(j0 + 2) * PAD + f] = a.z + b.z;
        s_w1[(j0 + 3) * PAD + f] = a.w + b.w;
        const float4 na = ((const float4*)Wn1)[i];
        s_wna[(j0 + 0) * PAD + f] = na.x;
        s_wna[(j0 + 1) * PAD + f] = na.y;
        s_wna[(j0 + 2) * PAD + f] = na.z;
        s_wna[(j0 + 3) * PAD + f] = na.w;
        const float4 nb = ((const float4*)Wn1)[256 + i];
        s_wnb[(j0 + 0) * PAD + f] = nb.x;
        s_wnb[(j0 + 1) * PAD + f] = nb.y;
        s_wnb[(j0 + 2) * PAD + f] = nb.z;
        s_wnb[(j0 + 3) * PAD + f] = nb.w;
        const float4 e2 = ((const float4*)We2)[i];
        s_we2[(j0 + 0) * PAD + f] = e2.x;
        s_we2[(j0 + 1) * PAD + f] = e2.y;
        s_we2[(j0 + 2) * PAD + f] = e2.z;
        s_we2[(j0 + 3) * PAD + f] = e2.w;
        const float4 n2 = ((const float4*)Wn2)[i];
        s_wn2[(j0 + 0) * PAD + f] = n2.x;
        s_wn2[(j0 + 1) * PAD + f] = n2.y;
        s_wn2[(j0 + 2) * PAD + f] = n2.z;
        s_wn2[(j0 + 3) * PAD + f] = n2.w;
    }
    if (tid < 32) s_wav[tid] = Wa[tid];

    __syncthreads();
    if (!has0) return;

    const int col = lane * PAD;

    // ---- layer 1 + S_h fused (one weight vec feeds both rows) ----
    float a00 = b1, a10 = 0.f, a01 = b1, a11 = 0.f;
    float p00 = 0.f, p10 = 0.f, p01 = 0.f, p11 = 0.f;
    #pragma unroll
    for (int q = 0; q < 8; ++q) {
        const float4 w1 = *(const float4*)&s_w1 [col + 4 * q];
        const float4 wn = *(const float4*)&s_wna[col + 4 * q];
        const float h00 = __shfl_sync(FULL, hv0, 4 * q + 0);
        const float h01 = __shfl_sync(FULL, hv0, 4 * q + 1);
        const float h02 = __shfl_sync(FULL, hv0, 4 * q + 2);
        const float h03 = __shfl_sync(FULL, hv0, 4 * q + 3);
        const float h10 = __shfl_sync(FULL, hv1, 4 * q + 0);
        const float h11 = __shfl_sync(FULL, hv1, 4 * q + 1);
        const float h12 = __shfl_sync(FULL, hv1, 4 * q + 2);
        const float h13 = __shfl_sync(FULL, hv1, 4 * q + 3);
        a00 += h00 * w1.x;  a10 += h01 * w1.y;  a00 += h02 * w1.z;  a10 += h03 * w1.w;
        a01 += h10 * w1.x;  a11 += h11 * w1.y;  a01 += h12 * w1.z;  a11 += h13 * w1.w;
        p00 += h00 * wn.x;  p10 += h01 * wn.y;  p00 += h02 * wn.z;  p10 += h03 * wn.w;
        p01 += h10 * wn.x;  p11 += h11 * wn.y;  p01 += h12 * wn.z;  p11 += h13 * wn.w;
    }
    const float t1_0 = silu_f(a00 + a10);
    const float t1_1 = silu_f(a01 + a11);
    const float sh0 = p00 + p10;
    const float sh1 = p01 + p11;

    // ---- layer 2 ----
    a00 = b2; a10 = 0.f; a01 = b2; a11 = 0.f;
    #pragma unroll
    for (int q = 0; q < 8; ++q) {
        const float4 w2 = *(const float4*)&s_we2[col + 4 * q];
        a00 += __shfl_sync(FULL, t1_0, 4 * q + 0) * w2.x;
        a10 += __shfl_sync(FULL, t1_0, 4 * q + 1) * w2.y;
        a00 += __shfl_sync(FULL, t1_0, 4 * q + 2) * w2.z;
        a10 += __shfl_sync(FULL, t1_0, 4 * q + 3) * w2.w;
        a01 += __shfl_sync(FULL, t1_1, 4 * q + 0) * w2.x;
        a11 += __shfl_sync(FULL, t1_1, 4 * q + 1) * w2.y;
        a01 += __shfl_sync(FULL, t1_1, 4 * q + 2) * w2.z;
        a11 += __shfl_sync(FULL, t1_1, 4 * q + 3) * w2.w;
    }
    const float t2_0 = silu_f(a00 + a10);
    const float t2_1 = silu_f(a01 + a11);

    // ---- S_t2 = t2 @ Wn1b with redundant per-lane att dot (no butterfly):
    //      the t2 broadcasts are shared between both accumulations; every
    //      lane computes the identical att sum in identical order.
    float p0b = 0.f, p1b = 0.f, p0c = 0.f, p1c = 0.f;
    float s00 = 0.f, s01 = 0.f, s10 = 0.f, s11 = 0.f;
    #pragma unroll
    for (int q = 0; q < 8; ++q) {
        const float4 wb = *(const float4*)&s_wnb[col + 4 * q];
        const float4 wv = *(const float4*)&s_wav[4 * q];          // broadcast
        const float u00 = __shfl_sync(FULL, t2_0, 4 * q + 0);
        const float u01 = __shfl_sync(FULL, t2_0, 4 * q + 1);
        const float u02 = __shfl_sync(FULL, t2_0, 4 * q + 2);
        const float u03 = __shfl_sync(FULL, t2_0, 4 * q + 3);
        const float u10 = __shfl_sync(FULL, t2_1, 4 * q + 0);
        const float u11 = __shfl_sync(FULL, t2_1, 4 * q + 1);
        const float u12 = __shfl_sync(FULL, t2_1, 4 * q + 2);
        const float u13 = __shfl_sync(FULL, t2_1, 4 * q + 3);
        p0b += u00 * wb.x;  p0c += u01 * wb.y;  p0b += u02 * wb.z;  p0c += u03 * wb.w;
        p1b += u10 * wb.x;  p1c += u11 * wb.y;  p1b += u12 * wb.z;  p1c += u13 * wb.w;
        s00 += u00 * wv.x;  s01 += u01 * wv.y;  s00 += u02 * wv.z;  s01 += u03 * wv.w;
        s10 += u10 * wv.x;  s11 += u11 * wv.y;  s10 += u12 * wv.z;  s11 += u13 * wv.w;
    }
    const float att0 = sigmoid_f((s00 + s01) + ba0);
    const float att1 = sigmoid_f((s10 + s11) + ba0);

    // ---- layer 3 epilogue ----
    const float t3_0 = silu_f(b3 + sh0 + att0 * (p0b + p0c));
    const float t3_1 = silu_f(b3 + sh1 + att1 * (p1b + p1c));

    // ---- layer 4 ----
    a00 = b4; a10 = 0.f; a01 = b4; a11 = 0.f;
    #pragma unroll
    for (int q = 0; q < 8; ++q) {
        const float4 w4 = *(const float4*)&s_wn2[col + 4 * q];
        a00 += __shfl_sync(FULL, t3_0, 4 * q + 0) * w4.x;
        a10 += __shfl_sync(FULL, t3_0, 4 * q + 1) * w4.y;
        a00 += __shfl_sync(FULL, t3_0, 4 * q + 2) * w4.z;
        a10 += __shfl_sync(FULL, t3_0, 4 * q + 3) * w4.w;
        a01 += __shfl_sync(FULL, t3_1, 4 * q + 0) * w4.x;
        a11 += __shfl_sync(FULL, t3_1, 4 * q + 1) * w4.y;
        a01 += __shfl_sync(FULL, t3_1, 4 * q + 2) * w4.z;
        a11 += __shfl_sync(FULL, t3_1, 4 * q + 3) * w4.w;
    }

    out[r0 * 32 + lane] = a00 + a10;
    if (has1) out[r1 * 32 + lane] = a01 + a11;
}

extern "C" void kernel_launch(void* const* d_in, const int* in_sizes, int n_in,
                              void* d_out, int out_size)
{
    const float* h   = (const float*)d_in[0];
    const float* x   = (const float*)d_in[1];
    const float* We1 = (const float*)d_in[2];
    const float* be1 = (const float*)d_in[3];
    const float* We2 = (const float*)d_in[4];
    const float* be2 = (const float*)d_in[5];
    const float* Wa  = (const float*)d_in[6];
    const float* ba  = (const float*)d_in[7];
    const float* Wn1 = (const float*)d_in[8];
    const float* bn1 = (const float*)d_in[9];
    const float* Wn2 = (const float*)d_in[10];
    const float* bn2 = (const float*)d_in[11];

    const int R = in_sizes[0] / 32;          // B*N rows
    float* out  = (float*)d_out;             // [R, 32]
    float* xout = out + (size_t)R * 32;      // [R, 3] passthrough

    const int threads = 32 * WARPS_PER_BLOCK;                       // 224
    const int blocks  = (R + ROWS_PER_BLOCK - 1) / ROWS_PER_BLOCK;  // 147
    egnn_diag_kernel<<<blocks, threads>>>(h, x, We1, be1, We2, be2, Wa, ba,
                                          Wn1, bn1, Wn2, bn2, out, xout, R);
}